// round 8
// baseline (speedup 1.0000x reference)
#include <cuda_runtime.h>
#include <cstddef>

// FastNGramLM advance, round 8: write-then-patch.
//  Phase 1 (chain):  threads 0..127 = 8 hyps x 16 lanes chase backoff chains;
//                    results stay in those threads' REGISTERS. acc -> smem.
//  Phase 2 (dense):  all 256 threads stream the pure dense output for all 8
//                    hyps: sc = acc_j + wf (regs), nx = const per thread.
//                    NO shared memory, NO barriers, max STG MLP.
//  Phase 3 (patch):  3 depth rounds (deepest first), barrier between rounds;
//                    each chain thread scatters its {score,next} to the
//                    overlaid labels. Shallowest round lands last ->
//                    first-found-wins semantics. Different hyps are disjoint;
//                    labels within one state are unique -> no intra-round races.
//
// Output: d_out[0..B*V) = scores f32, d_out[B*V..2BV) = next as exact f32.

#define VMAX  1024
#define DEPTH 3
#define ARCS  16
#define HPB   8
#define TPB   256

__global__ __launch_bounds__(TPB, 7)
void ngram_fused_kernel(const float* __restrict__ arcs_weights,
                        const float* __restrict__ backoff_weights,
                        const int*   __restrict__ ilabels,
                        const int*   __restrict__ to_states,
                        const int*   __restrict__ backoff_to,
                        const int*   __restrict__ state_start,
                        const int*   __restrict__ state_end,
                        const int*   __restrict__ states,
                        float*       __restrict__ out_scores,
                        float*       __restrict__ out_next,
                        int B, int V)
{
    __shared__ float s_acc[HPB];

    const int tid = threadIdx.x;
    const int h0  = blockIdx.x * HPB;

    // ---- dense fallback -> registers ----
    const float4 wf  = __ldg((const float4*)arcs_weights + tid);
    const int4   nfi = __ldg((const int4*)  to_states    + tid);
    float4 nfv;
    nfv.x = (float)nfi.x; nfv.y = (float)nfi.y;
    nfv.z = (float)nfi.z; nfv.w = (float)nfi.w;

    // ---- chain phase: threads 0..127, results in registers ----
    int   lab[DEPTH];
    float scr[DEPTH];
    float nxf[DEPTH];
    if (tid < HPB * ARCS) {
        const int j    = tid >> 4;
        const int lane = tid & 15;
        const int h    = h0 + j;
        int   cur = (h < B) ? __ldg(&states[h]) : 0;
        float acc = 0.0f;
        #pragma unroll
        for (int d = 0; d < DEPTH; ++d) {
            lab[d] = -1; scr[d] = 0.0f; nxf[d] = 0.0f;
            if (cur != 0) {                    // START == 0
                const int st  = __ldg(&state_start[cur]);
                const int en  = __ldg(&state_end[cur]);
                const int idx = st + lane;
                if (idx < en) {
                    lab[d] = __ldg(&ilabels[idx]);
                    scr[d] = acc + __ldg(&arcs_weights[idx]);
                    nxf[d] = (float)__ldg(&to_states[idx]);
                }
                acc += __ldg(&backoff_weights[cur]);
                cur  = __ldg(&backoff_to[cur]);
            }
        }
        if (lane == 0) s_acc[j] = acc;
    }
    __syncthreads();   // s_acc ready

    // ---- dense streaming phase: no smem, no barriers ----
    const int lab0 = tid * 4;
    #pragma unroll
    for (int j = 0; j < HPB; ++j) {
        const int h = h0 + j;
        if (h >= B) break;
        const float  acc  = s_acc[j];
        const size_t base = (size_t)h * (size_t)V + lab0;

        float4 sc;
        sc.x = acc + wf.x; sc.y = acc + wf.y;
        sc.z = acc + wf.z; sc.w = acc + wf.w;
        *(float4*)&out_scores[base] = sc;
        *(float4*)&out_next  [base] = nfv;
    }
    __syncthreads();   // dense writes ordered before patches

    // ---- patch phase: deepest -> shallowest, barrier-ordered WAW ----
    const int    jh    = tid >> 4;
    const size_t hbase = (size_t)(h0 + jh) * (size_t)V;
    const bool   owner = (tid < HPB * ARCS) && (h0 + jh < B);

    #pragma unroll
    for (int d = DEPTH - 1; d >= 0; --d) {
        if (owner && lab[d] >= 0) {
            out_scores[hbase + lab[d]] = scr[d];
            out_next  [hbase + lab[d]] = nxf[d];
        }
        if (d > 0) __syncthreads();   // order depth d after d-1's future write
    }
}

extern "C" void kernel_launch(void* const* d_in, const int* in_sizes, int n_in,
                              void* d_out, int out_size)
{
    // Classify inputs by element count (robust to metadata ordering):
    //   arcs group (3x largest):  arcs_weights, ilabels, to_states
    //   state group (4x middle):  backoff_weights, backoff_to, start, end
    //   states: the remaining batch-sized array
    long long max_sz = 0;
    for (int i = 0; i < n_in; ++i)
        if ((long long)in_sizes[i] > max_sz) max_sz = in_sizes[i];

    long long arc_sz = max_sz;
    long long n_sz = -1;
    for (int i = 0; i < n_in; ++i) {
        int cnt = 0;
        for (int j = 0; j < n_in; ++j)
            if (in_sizes[j] == in_sizes[i]) ++cnt;
        if (cnt == 4) { n_sz = in_sizes[i]; break; }
    }

    const void* arc_grp[3];  int na = 0;
    const void* st_grp[4];   int ns = 0;
    const void* states_ptr = nullptr;
    long long B = 0;
    for (int i = 0; i < n_in; ++i) {
        if (in_sizes[i] == arc_sz && na < 3)      arc_grp[na++] = d_in[i];
        else if (in_sizes[i] == n_sz && ns < 4)   st_grp[ns++]  = d_in[i];
        else { states_ptr = d_in[i]; B = in_sizes[i]; }
    }

    const float* arcs_weights    = (const float*)arc_grp[0];
    const int*   ilabels         = (const int*)  arc_grp[1];
    const int*   to_states       = (const int*)  arc_grp[2];
    const float* backoff_weights = (const float*)st_grp[0];
    const int*   backoff_to      = (const int*)  st_grp[1];
    const int*   state_start     = (const int*)  st_grp[2];
    const int*   state_end       = (const int*)  st_grp[3];
    const int*   states          = (const int*)  states_ptr;

    const long long V = (long long)out_size / (2 * B);
    float* out_scores = (float*)d_out;
    float* out_next   = (float*)d_out + (size_t)B * (size_t)V;

    const int grid = (int)((B + HPB - 1) / HPB);
    ngram_fused_kernel<<<grid, TPB>>>(
        arcs_weights, backoff_weights, ilabels, to_states,
        backoff_to, state_start, state_end, states,
        out_scores, out_next, (int)B, (int)V);
}

// round 9
// speedup vs baseline: 1.1128x; 1.1128x over previous
#include <cuda_runtime.h>
#include <cstddef>
#include <cstdint>

// FastNGramLM advance, round 9: smem staging + TMA bulk stores.
//  Phase 1 (chain):  threads 0..127 = 8 hyps x 16 lanes chase backoff chains;
//                    overlay records stay in registers. acc -> smem.
//  Per hypothesis (double-buffered 8KB smem staging):
//    build:  all 256 threads STS.128 dense row {acc+wf, next_f} into buf[p]
//    patch:  owning warp scatters <=48 overlay entries (reverse depth,
//            syncwarp-ordered, shallow-last = first-found-wins)
//    ship:   tid0: fence.proxy.async + 2x cp.async.bulk (4KB) + commit;
//            wait_group.read <=1 recycles the other buffer.
//  Global stores never touch the per-thread STG path -> LSU issue cost gone;
//  output moves at LTS cap via the async proxy.
//
// Output: d_out[0..B*V) = scores f32, d_out[B*V..2BV) = next as exact f32.

#define VMAX  1024
#define DEPTH 3
#define ARCS  16
#define HPB   8
#define TPB   256

__device__ __forceinline__ uint32_t smem_u32(const void* p) {
    return (uint32_t)__cvta_generic_to_shared(p);
}

__global__ __launch_bounds__(TPB, 7)
void ngram_fused_kernel(const float* __restrict__ arcs_weights,
                        const float* __restrict__ backoff_weights,
                        const int*   __restrict__ ilabels,
                        const int*   __restrict__ to_states,
                        const int*   __restrict__ backoff_to,
                        const int*   __restrict__ state_start,
                        const int*   __restrict__ state_end,
                        const int*   __restrict__ states,
                        float*       __restrict__ out_scores,
                        float*       __restrict__ out_next,
                        int B, int V)
{
    __shared__ __align__(128) float s_sc[2][VMAX];   // staging: scores
    __shared__ __align__(128) float s_nx[2][VMAX];   // staging: next (as f32)
    __shared__ float s_acc[HPB];

    const int tid = threadIdx.x;
    const int h0  = blockIdx.x * HPB;

    // ---- dense fallback -> registers ----
    const float4 wf  = __ldg((const float4*)arcs_weights + tid);
    const int4   nfi = __ldg((const int4*)  to_states    + tid);
    float4 nfv;
    nfv.x = (float)nfi.x; nfv.y = (float)nfi.y;
    nfv.z = (float)nfi.z; nfv.w = (float)nfi.w;

    // ---- chain phase: threads 0..127, results in registers ----
    int   lab[DEPTH];
    float scr[DEPTH];
    float nxf[DEPTH];
    if (tid < HPB * ARCS) {
        const int j    = tid >> 4;
        const int lane = tid & 15;
        const int h    = h0 + j;
        int   cur = (h < B) ? __ldg(&states[h]) : 0;
        float acc = 0.0f;
        #pragma unroll
        for (int d = 0; d < DEPTH; ++d) {
            lab[d] = -1; scr[d] = 0.0f; nxf[d] = 0.0f;
            if (cur != 0) {                    // START == 0
                const int st  = __ldg(&state_start[cur]);
                const int en  = __ldg(&state_end[cur]);
                const int idx = st + lane;
                if (idx < en) {
                    lab[d] = __ldg(&ilabels[idx]);
                    scr[d] = acc + __ldg(&arcs_weights[idx]);
                    nxf[d] = (float)__ldg(&to_states[idx]);
                }
                acc += __ldg(&backoff_weights[cur]);
                cur  = __ldg(&backoff_to[cur]);
            }
        }
        if (lane == 0) s_acc[j] = acc;
    }
    __syncthreads();   // s_acc ready

    const int lab0 = tid * 4;

    for (int j = 0; j < HPB; ++j) {
        const int h = h0 + j;
        if (h >= B) break;
        const int p = j & 1;

        // ---- build dense row into staging buffer p ----
        const float acc = s_acc[j];
        float4 sc;
        sc.x = acc + wf.x; sc.y = acc + wf.y;
        sc.z = acc + wf.z; sc.w = acc + wf.w;
        *(float4*)&s_sc[p][lab0] = sc;
        *(float4*)&s_nx[p][lab0] = nfv;
        __syncthreads();   // dense staging visible

        // ---- patch: warp (j>>1) owns hyp j (its lanes (j&1)*16..+15) ----
        if ((tid >> 5) == (j >> 1)) {          // uniform across the warp
            const bool mine = ((tid >> 4) & 1) == (j & 1);
            #pragma unroll
            for (int d = DEPTH - 1; d >= 0; --d) {   // shallow lands last
                if (mine && lab[d] >= 0) {
                    s_sc[p][lab[d]] = scr[d];
                    s_nx[p][lab[d]] = nxf[d];
                }
                __syncwarp();                  // order depth rounds
            }
        }
        __syncthreads();   // patches visible to the issuing thread

        // ---- ship via async bulk copy; recycle other buffer ----
        if (tid == 0) {
            asm volatile("fence.proxy.async.shared::cta;" ::: "memory");
            const uint32_t ssc = smem_u32(&s_sc[p][0]);
            const uint32_t snx = smem_u32(&s_nx[p][0]);
            const size_t   row = (size_t)h * (size_t)V;
            asm volatile(
                "cp.async.bulk.global.shared::cta.bulk_group [%0], [%1], %2;"
                :: "l"(out_scores + row), "r"(ssc), "r"(V * 4) : "memory");
            asm volatile(
                "cp.async.bulk.global.shared::cta.bulk_group [%0], [%1], %2;"
                :: "l"(out_next + row), "r"(snx), "r"(V * 4) : "memory");
            asm volatile("cp.async.bulk.commit_group;" ::: "memory");
            // allow 1 group in flight (the other buffer); older reads done
            asm volatile("cp.async.bulk.wait_group.read 1;" ::: "memory");
        }
        __syncthreads();   // buffer p^1 free for next iteration's build
    }

    // drain remaining bulk groups before exit
    if (tid == 0)
        asm volatile("cp.async.bulk.wait_group 0;" ::: "memory");
}

extern "C" void kernel_launch(void* const* d_in, const int* in_sizes, int n_in,
                              void* d_out, int out_size)
{
    // Classify inputs by element count (robust to metadata ordering):
    //   arcs group (3x largest):  arcs_weights, ilabels, to_states
    //   state group (4x middle):  backoff_weights, backoff_to, start, end
    //   states: the remaining batch-sized array
    long long max_sz = 0;
    for (int i = 0; i < n_in; ++i)
        if ((long long)in_sizes[i] > max_sz) max_sz = in_sizes[i];

    long long arc_sz = max_sz;
    long long n_sz = -1;
    for (int i = 0; i < n_in; ++i) {
        int cnt = 0;
        for (int j = 0; j < n_in; ++j)
            if (in_sizes[j] == in_sizes[i]) ++cnt;
        if (cnt == 4) { n_sz = in_sizes[i]; break; }
    }

    const void* arc_grp[3];  int na = 0;
    const void* st_grp[4];   int ns = 0;
    const void* states_ptr = nullptr;
    long long B = 0;
    for (int i = 0; i < n_in; ++i) {
        if (in_sizes[i] == arc_sz && na < 3)      arc_grp[na++] = d_in[i];
        else if (in_sizes[i] == n_sz && ns < 4)   st_grp[ns++]  = d_in[i];
        else { states_ptr = d_in[i]; B = in_sizes[i]; }
    }

    const float* arcs_weights    = (const float*)arc_grp[0];
    const int*   ilabels         = (const int*)  arc_grp[1];
    const int*   to_states       = (const int*)  arc_grp[2];
    const float* backoff_weights = (const float*)st_grp[0];
    const int*   backoff_to      = (const int*)  st_grp[1];
    const int*   state_start     = (const int*)  st_grp[2];
    const int*   state_end       = (const int*)  st_grp[3];
    const int*   states          = (const int*)  states_ptr;

    const long long V = (long long)out_size / (2 * B);
    float* out_scores = (float*)d_out;
    float* out_next   = (float*)d_out + (size_t)B * (size_t)V;

    const int grid = (int)((B + HPB - 1) / HPB);
    ngram_fused_kernel<<<grid, TPB>>>(
        arcs_weights, backoff_weights, ilabels, to_states,
        backoff_to, state_start, state_end, states,
        out_scores, out_next, (int)B, (int)V);
}